// round 4
// baseline (speedup 1.0000x reference)
#include <cuda_runtime.h>
#include <cstddef>

// Sparsemax over last dim: rows of D=512 fp32, one warp per row.
// Michelot exact fixed-point projection onto the simplex:
//   tau0 = (sum(x) - 1)/D ; repeat S={x>tau}, tau=(sum_S - 1)/|S| until |S| stable.

static constexpr int D = 512;          // elements per row
static constexpr int VPT = 4;          // float4 loads per thread (4*4*32 = 512)

__global__ __launch_bounds__(256) void sparsemax_kernel(
    const float* __restrict__ x, float* __restrict__ y, int nrows)
{
    const int gwarp = (blockIdx.x * blockDim.x + threadIdx.x) >> 5;
    if (gwarp >= nrows) return;
    const int lane = threadIdx.x & 31;

    const float4* __restrict__ xr =
        reinterpret_cast<const float4*>(x + (size_t)gwarp * D);
    float4* __restrict__ yr =
        reinterpret_cast<float4*>(y + (size_t)gwarp * D);

    // Load 16 values (4 coalesced float4s) and compute full-row sum.
    float4 v[VPT];
    float sum = 0.0f;
#pragma unroll
    for (int j = 0; j < VPT; j++) {
        float4 t = xr[lane + 32 * j];
        v[j] = t;
        sum += (t.x + t.y) + (t.z + t.w);
    }
#pragma unroll
    for (int o = 16; o > 0; o >>= 1)
        sum += __shfl_xor_sync(0xffffffffu, sum, o);

    float tau = (sum - 1.0f) * (1.0f / D);
    int count = D;

    // Michelot iteration: support shrinks monotonically; terminates when
    // the support size is unchanged (=> same set => tau is the fixed point).
    for (;;) {
        float s = 0.0f;
        int c = 0;
#pragma unroll
        for (int j = 0; j < VPT; j++) {
            if (v[j].x > tau) { s += v[j].x; c++; }
            if (v[j].y > tau) { s += v[j].y; c++; }
            if (v[j].z > tau) { s += v[j].z; c++; }
            if (v[j].w > tau) { s += v[j].w; c++; }
        }
#pragma unroll
        for (int o = 16; o > 0; o >>= 1) {
            s += __shfl_xor_sync(0xffffffffu, s, o);
            c += __shfl_xor_sync(0xffffffffu, c, o);
        }
        if (c == count) break;     // fixed point reached; current tau exact
        count = c;
        tau = (s - 1.0f) / (float)c;
    }

    // Write max(0, x - tau) with vector stores.
#pragma unroll
    for (int j = 0; j < VPT; j++) {
        float4 t = v[j];
        float4 o;
        o.x = fmaxf(0.0f, t.x - tau);
        o.y = fmaxf(0.0f, t.y - tau);
        o.z = fmaxf(0.0f, t.z - tau);
        o.w = fmaxf(0.0f, t.w - tau);
        yr[lane + 32 * j] = o;
    }
}

extern "C" void kernel_launch(void* const* d_in, const int* in_sizes, int n_in,
                              void* d_out, int out_size)
{
    const float* x = (const float*)d_in[0];
    float* y = (float*)d_out;
    const int nrows = in_sizes[0] / D;          // 32*4096 = 131072
    const int warps_per_block = 8;              // 256 threads
    const int blocks = (nrows + warps_per_block - 1) / warps_per_block;
    sparsemax_kernel<<<blocks, warps_per_block * 32>>>(x, y, nrows);
}

// round 5
// speedup vs baseline: 1.3707x; 1.3707x over previous
#include <cuda_runtime.h>
#include <cstddef>

// Sparsemax over last dim: rows of D=512 fp32, one warp per row.
// Warm-started Michelot exact simplex projection:
//   tau* >= max(x) - 1  (since max(x) - tau* <= sum(max(x - tau*, 0)) = 1)
//   start tau0 = M - 1; S0 = {x > tau0} is tiny (~5 elems for N(0,1)).
//   tau1 = (sum_{S0} - 1)/|S0| >= tau0 (max element supplies the +1), so the
//   standard monotone-shrinking-support argument holds and the count-stable
//   termination yields the exact tau*.

static constexpr int D = 512;          // elements per row
static constexpr int VPT = 4;          // float4 loads per thread (4*4*32 = 512)

__global__ __launch_bounds__(256) void sparsemax_kernel(
    const float* __restrict__ x, float* __restrict__ y, int nrows)
{
    const int gwarp = (blockIdx.x * blockDim.x + threadIdx.x) >> 5;
    if (gwarp >= nrows) return;
    const int lane = threadIdx.x & 31;

    const float4* __restrict__ xr =
        reinterpret_cast<const float4*>(x) + (size_t)gwarp * (D / 4);
    float4* __restrict__ yr =
        reinterpret_cast<float4*>(y) + (size_t)gwarp * (D / 4);

    // Load 16 values (4 coalesced, streaming float4s); track row max.
    float4 v[VPT];
    float m = -3.402823466e38f;
#pragma unroll
    for (int j = 0; j < VPT; j++) {
        float4 t = __ldcs(&xr[lane + 32 * j]);
        v[j] = t;
        m = fmaxf(m, fmaxf(fmaxf(t.x, t.y), fmaxf(t.z, t.w)));
    }
#pragma unroll
    for (int o = 16; o > 0; o >>= 1)
        m = fmaxf(m, __shfl_xor_sync(0xffffffffu, m, o));

    // Warm start: tau0 = M - 1 is a valid lower bound on tau*.
    float tau = m - 1.0f;
    int prev = -1;

    for (;;) {
        float s = 0.0f;
        int c = 0;
#pragma unroll
        for (int j = 0; j < VPT; j++) {
            if (v[j].x > tau) { s += v[j].x; c++; }
            if (v[j].y > tau) { s += v[j].y; c++; }
            if (v[j].z > tau) { s += v[j].z; c++; }
            if (v[j].w > tau) { s += v[j].w; c++; }
        }
#pragma unroll
        for (int o = 16; o > 0; o >>= 1)
            s += __shfl_xor_sync(0xffffffffu, s, o);
        c = __reduce_add_sync(0xffffffffu, c);   // REDUX.SUM, 1 instr

        if (c == prev) break;   // same count => same level set => fixed point
        prev = c;
        tau = (s - 1.0f) / (float)c;
    }

    // Write max(0, x - tau) with streaming vector stores.
#pragma unroll
    for (int j = 0; j < VPT; j++) {
        float4 t = v[j];
        float4 o;
        o.x = fmaxf(0.0f, t.x - tau);
        o.y = fmaxf(0.0f, t.y - tau);
        o.z = fmaxf(0.0f, t.z - tau);
        o.w = fmaxf(0.0f, t.w - tau);
        __stcs(&yr[lane + 32 * j], o);
    }
}

extern "C" void kernel_launch(void* const* d_in, const int* in_sizes, int n_in,
                              void* d_out, int out_size)
{
    const float* x = (const float*)d_in[0];
    float* y = (float*)d_out;
    const int nrows = in_sizes[0] / D;          // 32*4096 = 131072
    const int warps_per_block = 8;              // 256 threads
    const int blocks = (nrows + warps_per_block - 1) / warps_per_block;
    sparsemax_kernel<<<blocks, warps_per_block * 32>>>(x, y, nrows);
}